// round 5
// baseline (speedup 1.0000x reference)
#include <cuda_runtime.h>
#include <cuda_bf16.h>

// MaxPool2d k=2 s=2 on fp32 NCHW (32, 96, 224, 224) -> (32, 96, 112, 112).
// DRAM-bound at ~7.08 TB/s (89% of peak); traffic is already minimal (771 MB).
// This round: symmetric 256-bit I/O. One thread = 8 output pixels:
//   4x ld.global.nc.v8.f32 (two rows x 64 B) -> 1x st.global.v8.f32 (32 B).
// Every warp-level load AND store is a fully contiguous 1024 B sweep,
// halving store transactions and giving the DRAM controller larger clean
// write bursts (fewer read/write turnarounds).
//
//   NC = 32*96 = 3072, H = W = 224, OH = OW = 112
//   v8-groups per output row = 112/8 = 14
//   total threads = 3072 * 112 * 14 = 4,816,896  (= 18816 blocks of 256)

#define NC_    3072
#define W_     224
#define OH_    112
#define OW8_   14            // 8-float groups per output row
#define TOTAL_ (NC_ * OH_ * OW8_)

__global__ __launch_bounds__(256)
void maxpool2x2_kernel(const float* __restrict__ x, float* __restrict__ out) {
    unsigned int idx = blockIdx.x * 256u + threadIdx.x;   // output v8-group index
    if (idx >= TOTAL_) return;

    unsigned int ox8 = idx % OW8_;           // which 8-float group within output row
    unsigned int t   = idx / OW8_;
    unsigned int oy  = t % OH_;
    unsigned int nc  = t / OH_;

    // Input: plane nc, rows 2*oy / 2*oy+1, float cols [16*ox8 .. +31]. 64 B aligned.
    const float* p0 = x + (size_t)nc * (W_ * W_) + (size_t)(2u * oy) * W_ + 16u * ox8;
    const float* p1 = p0 + W_;

    float a[16], b[16];
    asm volatile("ld.global.nc.v8.f32 {%0,%1,%2,%3,%4,%5,%6,%7}, [%8];"
        : "=f"(a[0]), "=f"(a[1]), "=f"(a[2]), "=f"(a[3]),
          "=f"(a[4]), "=f"(a[5]), "=f"(a[6]), "=f"(a[7]) : "l"(p0));
    asm volatile("ld.global.nc.v8.f32 {%0,%1,%2,%3,%4,%5,%6,%7}, [%8];"
        : "=f"(a[8]), "=f"(a[9]), "=f"(a[10]), "=f"(a[11]),
          "=f"(a[12]), "=f"(a[13]), "=f"(a[14]), "=f"(a[15]) : "l"(p0 + 8));
    asm volatile("ld.global.nc.v8.f32 {%0,%1,%2,%3,%4,%5,%6,%7}, [%8];"
        : "=f"(b[0]), "=f"(b[1]), "=f"(b[2]), "=f"(b[3]),
          "=f"(b[4]), "=f"(b[5]), "=f"(b[6]), "=f"(b[7]) : "l"(p1));
    asm volatile("ld.global.nc.v8.f32 {%0,%1,%2,%3,%4,%5,%6,%7}, [%8];"
        : "=f"(b[8]), "=f"(b[9]), "=f"(b[10]), "=f"(b[11]),
          "=f"(b[12]), "=f"(b[13]), "=f"(b[14]), "=f"(b[15]) : "l"(p1 + 8));

    float r[8];
#pragma unroll
    for (int i = 0; i < 8; i++)
        r[i] = fmaxf(fmaxf(a[2*i], a[2*i+1]), fmaxf(b[2*i], b[2*i+1]));

    float* q = out + (size_t)idx * 8;   // 32 B aligned
    asm volatile("st.global.v8.f32 [%0], {%1,%2,%3,%4,%5,%6,%7,%8};"
        :: "l"(q),
           "f"(r[0]), "f"(r[1]), "f"(r[2]), "f"(r[3]),
           "f"(r[4]), "f"(r[5]), "f"(r[6]), "f"(r[7])
        : "memory");
}

extern "C" void kernel_launch(void* const* d_in, const int* in_sizes, int n_in,
                              void* d_out, int out_size) {
    const float* x = (const float*)d_in[0];
    float* out = (float*)d_out;
    const int threads = 256;
    const int blocks = (TOTAL_ + threads - 1) / threads;   // 18816
    maxpool2x2_kernel<<<blocks, threads>>>(x, out);
}

// round 7
// speedup vs baseline: 1.0164x; 1.0164x over previous
#include <cuda_runtime.h>
#include <cuda_bf16.h>

// MaxPool2d k=2 s=2 on fp32 NCHW (32, 96, 224, 224) -> (32, 96, 112, 112).
// DRAM-bound at the controller ceiling (~7.05-7.08 TB/s, 88-89% of spec)
// across all load/store-width variants; traffic is minimal (771 MB).
// Final shape = best variant (R2): one thread per output float4,
// 2x LDG.128 per input row, 1x STG.128; 24 regs, occ ~80%.
// This round's tweaks: evict-first streaming hints on both zero-reuse
// streams (__ldcs/__stcs) + 512-thread blocks.
//
//   NC = 32*96 = 3072, H = W = 224, OH = OW = 112
//   output float4s per row = 112/4 = 28
//   total threads = 3072 * 112 * 28 = 9,633,792  (= 18816 blocks of 512)

#define NC_    3072
#define W_     224
#define OH_    112
#define OW4_   28            // float4s per output row
#define ROWF4_ (W_ / 4)      // 56 float4s per input row
#define TOTAL_ (NC_ * OH_ * OW4_)

__global__ __launch_bounds__(512)
void maxpool2x2_kernel(const float4* __restrict__ x, float4* __restrict__ out) {
    unsigned int idx = blockIdx.x * 512u + threadIdx.x;   // == output float4 index
    if (idx >= TOTAL_) return;

    unsigned int ox4 = idx % OW4_;           // which float4 within output row
    unsigned int t   = idx / OW4_;
    unsigned int oy  = t % OH_;
    unsigned int nc  = t / OH_;

    // Input as float4 indices: plane = nc*12544, rows 2*oy / 2*oy+1, col 2*ox4.
    size_t base = (size_t)nc * (W_ * W_ / 4) + (size_t)(2u * oy) * ROWF4_ + 2u * ox4;

    float4 a0 = __ldcs(x + base);               // row 2*oy,   floats [8*ox4 .. +3]
    float4 a1 = __ldcs(x + base + 1);           // row 2*oy,   floats [+4 .. +7]
    float4 b0 = __ldcs(x + base + ROWF4_);      // row 2*oy+1, floats [8*ox4 .. +3]
    float4 b1 = __ldcs(x + base + ROWF4_ + 1);  // row 2*oy+1, floats [+4 .. +7]

    float4 r;
    r.x = fmaxf(fmaxf(a0.x, a0.y), fmaxf(b0.x, b0.y));
    r.y = fmaxf(fmaxf(a0.z, a0.w), fmaxf(b0.z, b0.w));
    r.z = fmaxf(fmaxf(a1.x, a1.y), fmaxf(b1.x, b1.y));
    r.w = fmaxf(fmaxf(a1.z, a1.w), fmaxf(b1.z, b1.w));

    __stcs(out + idx, r);
}

extern "C" void kernel_launch(void* const* d_in, const int* in_sizes, int n_in,
                              void* d_out, int out_size) {
    const float4* x = (const float4*)d_in[0];
    float4* out = (float4*)d_out;
    const int threads = 512;
    const int blocks = (TOTAL_ + threads - 1) / threads;   // 18816
    maxpool2x2_kernel<<<blocks, threads>>>(x, out);
}